// round 3
// baseline (speedup 1.0000x reference)
#include <cuda_runtime.h>

#define NPIX 22500
#define NB 32
#define NCHUNK 6
#define CHUNK 3750   // 22500 / 6
#define TPB 256
#define HB 64
#define LOB (-3.0f)
#define STEP (6.0f / 63.0f)
#define INV_SIG2 2500.0f   // 1 / 0.02^2

typedef unsigned long long ull;

// Scratch (no allocations allowed): prep data + per-chunk partial histograms
__device__ float g_prep[3 * NB * NPIX];                    // d01, d02, Iy planes
__device__ float g_part[NB * 3 * NCHUNK * HB * HB];        // partial hists

__device__ __forceinline__ float kq(float d) {
    // inverse-quadratic soft-bin kernel: 1 / (1 + d^2 / sigma^2)
    float q = fmaf(d * d, INV_SIG2, 1.0f);
    float r;
    asm("rcp.approx.f32 %0, %1;" : "=f"(r) : "f"(q));
    return r;
}

// ---------------------------------------------------------------------------
// Kernel 1: per-pixel prep — clip, logs, intensity
// ---------------------------------------------------------------------------
__global__ void __launch_bounds__(TPB) prep_kernel(const float* __restrict__ x) {
    int idx = blockIdx.x * blockDim.x + threadIdx.x;
    if (idx >= NB * NPIX) return;
    int b = idx / NPIX;
    int p = idx - b * NPIX;
    const float* xb = x + (size_t)b * 3 * NPIX;
    float r  = fminf(fmaxf(xb[p],            0.0f), 1.0f);
    float g  = fminf(fmaxf(xb[NPIX + p],     0.0f), 1.0f);
    float bl = fminf(fmaxf(xb[2 * NPIX + p], 0.0f), 1.0f);
    float iy = sqrtf(fmaf(r, r, fmaf(g, g, fmaf(bl, bl, 1e-6f))));
    float l0 = logf(r  + 1e-6f);
    float l1 = logf(g  + 1e-6f);
    float l2 = logf(bl + 1e-6f);
    g_prep[idx]                 = l0 - l1;   // d01
    g_prep[NB * NPIX + idx]     = l0 - l2;   // d02
    g_prep[2 * NB * NPIX + idx] = iy;
}

// ---------------------------------------------------------------------------
// Kernel 2: main — per (b, c, chunk) CTA, 32-pixel tiles
//   sKu2[pix][u] holds {iy*Ku, iy*Ku} pre-splatted as 64-bit -> consume loop
//   needs zero packing MOVs: 6x LDS.64 + 8x fma.rn.f32x2 per pixel.
// ---------------------------------------------------------------------------
__global__ void __launch_bounds__(TPB, 4) hist_kernel() {
    __shared__ ull   sKu2[32][64];   // splatted {iy*Ku, iy*Ku}, 16 KB
    __shared__ float sKv[32][64];    // Kv, 8 KB

    int cta   = blockIdx.x;           // 0 .. 96*NCHUNK-1
    int chunk = cta % NCHUNK;
    int bc    = cta / NCHUNK;
    int b     = bc / 3;
    int c     = bc - b * 3;

    int t   = threadIdx.x;
    int tu  = t >> 4;                 // 0..15 -> u-tile
    int tv  = t & 15;                 // 0..15 -> v-tile

    // gen-phase mapping: warps 0-3 -> Ku, warps 4-7 -> Kv (warp-uniform paths)
    bool isKu = (t < 128);
    int  s    = t & 127;
    int  pix  = s >> 2;               // 0..31
    int  bin0 = (s & 3) * 16;         // 0,16,32,48

    ull acc[4][2];
    #pragma unroll
    for (int i = 0; i < 4; ++i) { acc[i][0] = 0ull; acc[i][1] = 0ull; }

    const float* pd01 = g_prep + (size_t)b * NPIX;
    const float* pd02 = pd01 + (size_t)NB * NPIX;
    const float* piy  = pd01 + (size_t)2 * NB * NPIX;
    int p0 = chunk * CHUNK;

    const int NTILES = (CHUNK + 31) / 32;   // 118 (last tile partial)
    for (int tile = 0; tile < NTILES; ++tile) {
        int p = p0 + tile * 32 + pix;
        float d01 = 0.0f, d02 = 0.0f, iy = 0.0f;
        if (p < p0 + CHUNK) {
            d01 = pd01[p];
            d02 = pd02[p];
            iy  = piy[p];    // OOB pixels keep iy=0 -> Ku row = 0 -> no contribution
        }
        float U, V;
        if (c == 0)      { U =  d01; V =  d02; }
        else if (c == 1) { U = -d01; V =  d02 - d01; }
        else             { U = -d02; V =  d01 - d02; }

        if (isKu) {
            float dBase = U - (LOB + (float)bin0 * STEP);
            #pragma unroll
            for (int q = 0; q < 8; ++q) {
                float v0 = kq(dBase - (float)(2 * q    ) * STEP) * iy;
                float v1 = kq(dBase - (float)(2 * q + 1) * STEP) * iy;
                float4 o; o.x = v0; o.y = v0; o.z = v1; o.w = v1;
                *reinterpret_cast<float4*>(&sKu2[pix][bin0 + 2 * q]) = o;
            }
        } else {
            float dBase = V - (LOB + (float)bin0 * STEP);
            #pragma unroll
            for (int q = 0; q < 4; ++q) {
                float4 o;
                o.x = kq(dBase - (float)(4 * q + 0) * STEP);
                o.y = kq(dBase - (float)(4 * q + 1) * STEP);
                o.z = kq(dBase - (float)(4 * q + 2) * STEP);
                o.w = kq(dBase - (float)(4 * q + 3) * STEP);
                *reinterpret_cast<float4*>(&sKv[pix][bin0 + 4 * q]) = o;
            }
        }
        __syncthreads();

        const ull*   kuP = &sKu2[0][tu * 4];
        const float* kvP = &sKv[0][tv * 4];
        #pragma unroll 8
        for (int pl = 0; pl < 32; ++pl) {
            ull a0 = kuP[pl * 64 + 0];
            ull a1 = kuP[pl * 64 + 1];
            ull a2 = kuP[pl * 64 + 2];
            ull a3 = kuP[pl * 64 + 3];
            ull kv01 = *reinterpret_cast<const ull*>(kvP + pl * 64);
            ull kv23 = *reinterpret_cast<const ull*>(kvP + pl * 64 + 2);
            asm("fma.rn.f32x2 %0, %1, %2, %0;" : "+l"(acc[0][0]) : "l"(a0), "l"(kv01));
            asm("fma.rn.f32x2 %0, %1, %2, %0;" : "+l"(acc[0][1]) : "l"(a0), "l"(kv23));
            asm("fma.rn.f32x2 %0, %1, %2, %0;" : "+l"(acc[1][0]) : "l"(a1), "l"(kv01));
            asm("fma.rn.f32x2 %0, %1, %2, %0;" : "+l"(acc[1][1]) : "l"(a1), "l"(kv23));
            asm("fma.rn.f32x2 %0, %1, %2, %0;" : "+l"(acc[2][0]) : "l"(a2), "l"(kv01));
            asm("fma.rn.f32x2 %0, %1, %2, %0;" : "+l"(acc[2][1]) : "l"(a2), "l"(kv23));
            asm("fma.rn.f32x2 %0, %1, %2, %0;" : "+l"(acc[3][0]) : "l"(a3), "l"(kv01));
            asm("fma.rn.f32x2 %0, %1, %2, %0;" : "+l"(acc[3][1]) : "l"(a3), "l"(kv23));
        }
        __syncthreads();
    }

    // write this CTA's 64x64 partial (deterministic, no atomics)
    float* base = g_part + (size_t)cta * (HB * HB);
    #pragma unroll
    for (int i = 0; i < 4; ++i) {
        int u = tu * 4 + i;
        #pragma unroll
        for (int jp = 0; jp < 2; ++jp) {
            int v = tv * 4 + jp * 2;
            *reinterpret_cast<ull*>(base + u * HB + v) = acc[i][jp];
        }
    }
}

// ---------------------------------------------------------------------------
// Kernel 3: reduce chunk partials, per-batch normalize, write output
// ---------------------------------------------------------------------------
__global__ void __launch_bounds__(TPB) finalize_kernel(float* __restrict__ out) {
    int b = blockIdx.x;
    int t = threadIdx.x;
    float vals[48];
    float local = 0.0f;
    #pragma unroll
    for (int j = 0; j < 48; ++j) {
        int vi = t + TPB * j;            // 0 .. 12287 = c*4096 + u*64 + v
        int c  = vi >> 12;
        int uv = vi & 4095;
        const float* part = g_part + (size_t)(b * 3 + c) * NCHUNK * 4096 + uv;
        float s = 0.0f;
        #pragma unroll
        for (int k = 0; k < NCHUNK; ++k) s += part[k * 4096];
        vals[j] = s;
        local  += s;
    }
    __shared__ float red[TPB];
    red[t] = local;
    __syncthreads();
    #pragma unroll
    for (int s = TPB / 2; s > 0; s >>= 1) {
        if (t < s) red[t] += red[t + s];
        __syncthreads();
    }
    float inv = 1.0f / (red[0] + 1e-6f);
    #pragma unroll
    for (int j = 0; j < 48; ++j) {
        out[(size_t)b * 12288 + t + TPB * j] = vals[j] * inv;
    }
}

// ---------------------------------------------------------------------------
extern "C" void kernel_launch(void* const* d_in, const int* in_sizes, int n_in,
                              void* d_out, int out_size) {
    const float* x = (const float*)d_in[0];
    float* out = (float*)d_out;
    prep_kernel<<<(NB * NPIX + TPB - 1) / TPB, TPB>>>(x);
    hist_kernel<<<NB * 3 * NCHUNK, TPB>>>();
    finalize_kernel<<<NB, TPB>>>(out);
}

// round 5
// speedup vs baseline: 1.5427x; 1.5427x over previous
#include <cuda_runtime.h>

#define NPIX 22500
#define NB 32
#define NCHUNK 6
#define CHUNK 3750   // 22500 / 6
#define TPB 256
#define HB 64
#define LOB (-3.0f)
#define STEP (6.0f / 63.0f)
#define INV_SIG2 2500.0f   // 1 / 0.02^2

typedef unsigned long long ull;

// Scratch (no allocations allowed): prep data + per-chunk partial histograms
__device__ float g_prep[3 * NB * NPIX];                          // d01, d02, Iy planes
__device__ float g_part[NB * 3 * NCHUNK * 2 * HB * HB];          // partial hists (2 halves/CTA)

__device__ __forceinline__ float kq(float d) {
    // inverse-quadratic soft-bin kernel: 1 / (1 + d^2 / sigma^2)
    float q = fmaf(d * d, INV_SIG2, 1.0f);
    float r;
    asm("rcp.approx.f32 %0, %1;" : "=f"(r) : "f"(q));
    return r;
}

// ---------------------------------------------------------------------------
// Kernel 1: per-pixel prep — clip, logs, intensity
// ---------------------------------------------------------------------------
__global__ void __launch_bounds__(TPB) prep_kernel(const float* __restrict__ x) {
    int idx = blockIdx.x * blockDim.x + threadIdx.x;
    if (idx >= NB * NPIX) return;
    int b = idx / NPIX;
    int p = idx - b * NPIX;
    const float* xb = x + (size_t)b * 3 * NPIX;
    float r  = fminf(fmaxf(xb[p],            0.0f), 1.0f);
    float g  = fminf(fmaxf(xb[NPIX + p],     0.0f), 1.0f);
    float bl = fminf(fmaxf(xb[2 * NPIX + p], 0.0f), 1.0f);
    float iy = sqrtf(fmaf(r, r, fmaf(g, g, fmaf(bl, bl, 1e-6f))));
    float l0 = logf(r  + 1e-6f);
    float l1 = logf(g  + 1e-6f);
    float l2 = logf(bl + 1e-6f);
    g_prep[idx]                 = l0 - l1;   // d01
    g_prep[NB * NPIX + idx]     = l0 - l2;   // d02
    g_prep[2 * NB * NPIX + idx] = iy;
}

// ---------------------------------------------------------------------------
// Kernel 2: main — per (b, c, chunk) CTA, 32-pixel tiles.
//   Consume: 256 threads = 2 pixel-halves x 128 threads; each thread owns a
//   4u x 8v register tile (v split-strided for bank-conflict-free LDS.128).
//   Per inner iter: 3 LDS.128 + 4 splat MOV + 16 fma.rn.f32x2  (32 FMAs).
// ---------------------------------------------------------------------------
__global__ void __launch_bounds__(TPB, 2) hist_kernel() {
    __shared__ float sKu[32][64];   // iy * Ku, 8 KB
    __shared__ float sKv[32][64];   // Kv, 8 KB

    int cta   = blockIdx.x;           // 0 .. 96*NCHUNK-1
    int chunk = cta % NCHUNK;
    int bc    = cta / NCHUNK;
    int b     = bc / 3;
    int c     = bc - b * 3;

    int t    = threadIdx.x;
    int half = t >> 7;                // pixel-half: 0 -> pix 0-15, 1 -> pix 16-31
    int rem  = t & 127;
    int tu   = rem >> 3;              // 0..15 : u-tile (4 u-bins)
    int tv8  = rem & 7;               // 0..7  : v-tile (8 v-bins, split-strided)

    // gen-phase mapping: warps 0-3 -> Ku, warps 4-7 -> Kv (warp-uniform paths)
    bool isKu = (t < 128);
    int  gpix = (t & 127) >> 2;       // 0..31
    int  bin0 = (t & 3) * 16;         // 0,16,32,48

    ull acc[4][4];                    // [u][ v-pair: lo01, lo23, hi01, hi23 ]
    #pragma unroll
    for (int i = 0; i < 4; ++i)
        #pragma unroll
        for (int j = 0; j < 4; ++j) acc[i][j] = 0ull;

    const float* pd01 = g_prep + (size_t)b * NPIX;
    const float* pd02 = pd01 + (size_t)NB * NPIX;
    const float* piy  = pd01 + (size_t)2 * NB * NPIX;
    int p0 = chunk * CHUNK;

    const int NTILES = (CHUNK + 31) / 32;   // 118 (last tile partial)
    for (int tile = 0; tile < NTILES; ++tile) {
        // ---- generate Ku/Kv tables for 32 pixels ----
        int p = p0 + tile * 32 + gpix;
        float d01 = 0.0f, d02 = 0.0f, iy = 0.0f;
        if (p < p0 + CHUNK) {
            d01 = pd01[p];
            d02 = pd02[p];
            iy  = piy[p];    // OOB pixels keep iy=0 -> Ku row = 0 -> no contribution
        }
        float U, V;
        if (c == 0)      { U =  d01; V =  d02; }
        else if (c == 1) { U = -d01; V =  d02 - d01; }
        else             { U = -d02; V =  d01 - d02; }

        if (isKu) {
            float dBase = U - (LOB + (float)bin0 * STEP);
            #pragma unroll
            for (int q = 0; q < 4; ++q) {
                float4 o;
                o.x = kq(dBase - (float)(4 * q + 0) * STEP) * iy;
                o.y = kq(dBase - (float)(4 * q + 1) * STEP) * iy;
                o.z = kq(dBase - (float)(4 * q + 2) * STEP) * iy;
                o.w = kq(dBase - (float)(4 * q + 3) * STEP) * iy;
                *reinterpret_cast<float4*>(&sKu[gpix][bin0 + 4 * q]) = o;
            }
        } else {
            float dBase = V - (LOB + (float)bin0 * STEP);
            #pragma unroll
            for (int q = 0; q < 4; ++q) {
                float4 o;
                o.x = kq(dBase - (float)(4 * q + 0) * STEP);
                o.y = kq(dBase - (float)(4 * q + 1) * STEP);
                o.z = kq(dBase - (float)(4 * q + 2) * STEP);
                o.w = kq(dBase - (float)(4 * q + 3) * STEP);
                *reinterpret_cast<float4*>(&sKv[gpix][bin0 + 4 * q]) = o;
            }
        }
        __syncthreads();

        // ---- consume: 16 pixels for this half, 4u x 8v per thread ----
        #pragma unroll
        for (int pl = 0; pl < 16; ++pl) {
            int px = half * 16 + pl;
            float4 a4 = *reinterpret_cast<const float4*>(&sKu[px][tu * 4]);
            ulonglong2 klo = *reinterpret_cast<const ulonglong2*>(&sKv[px][tv8 * 4]);
            ulonglong2 khi = *reinterpret_cast<const ulonglong2*>(&sKv[px][32 + tv8 * 4]);
            float av[4] = {a4.x, a4.y, a4.z, a4.w};
            #pragma unroll
            for (int i = 0; i < 4; ++i) {
                ull a2;
                asm("mov.b64 %0, {%1, %1};" : "=l"(a2) : "r"(__float_as_uint(av[i])));
                asm("fma.rn.f32x2 %0, %1, %2, %0;" : "+l"(acc[i][0]) : "l"(a2), "l"(klo.x));
                asm("fma.rn.f32x2 %0, %1, %2, %0;" : "+l"(acc[i][1]) : "l"(a2), "l"(klo.y));
                asm("fma.rn.f32x2 %0, %1, %2, %0;" : "+l"(acc[i][2]) : "l"(a2), "l"(khi.x));
                asm("fma.rn.f32x2 %0, %1, %2, %0;" : "+l"(acc[i][3]) : "l"(a2), "l"(khi.y));
            }
        }
        __syncthreads();
    }

    // write this (CTA, half)'s 64x64 partial (deterministic, no atomics)
    float* base = g_part + ((size_t)cta * 2 + half) * (HB * HB);
    #pragma unroll
    for (int i = 0; i < 4; ++i) {
        int u = tu * 4 + i;
        ulonglong2 lo; lo.x = acc[i][0]; lo.y = acc[i][1];
        ulonglong2 hi; hi.x = acc[i][2]; hi.y = acc[i][3];
        *reinterpret_cast<ulonglong2*>(base + u * HB + tv8 * 4)      = lo;
        *reinterpret_cast<ulonglong2*>(base + u * HB + 32 + tv8 * 4) = hi;
    }
}

// ---------------------------------------------------------------------------
// Kernel 3: reduce 12 partials per (b,c), per-batch normalize, write output
// ---------------------------------------------------------------------------
#define NPART (NCHUNK * 2)
__global__ void __launch_bounds__(TPB) finalize_kernel(float* __restrict__ out) {
    int b = blockIdx.x;
    int t = threadIdx.x;
    float vals[48];
    float local = 0.0f;
    #pragma unroll
    for (int j = 0; j < 48; ++j) {
        int vi = t + TPB * j;            // 0 .. 12287 = c*4096 + u*64 + v
        int c  = vi >> 12;
        int uv = vi & 4095;
        const float* part = g_part + (size_t)(b * 3 + c) * NPART * 4096 + uv;
        float s = 0.0f;
        #pragma unroll
        for (int k = 0; k < NPART; ++k) s += part[k * 4096];
        vals[j] = s;
        local  += s;
    }
    __shared__ float red[TPB];
    red[t] = local;
    __syncthreads();
    #pragma unroll
    for (int s = TPB / 2; s > 0; s >>= 1) {
        if (t < s) red[t] += red[t + s];
        __syncthreads();
    }
    float inv = 1.0f / (red[0] + 1e-6f);
    #pragma unroll
    for (int j = 0; j < 48; ++j) {
        out[(size_t)b * 12288 + t + TPB * j] = vals[j] * inv;
    }
}

// ---------------------------------------------------------------------------
extern "C" void kernel_launch(void* const* d_in, const int* in_sizes, int n_in,
                              void* d_out, int out_size) {
    const float* x = (const float*)d_in[0];
    float* out = (float*)d_out;
    prep_kernel<<<(NB * NPIX + TPB - 1) / TPB, TPB>>>(x);
    hist_kernel<<<NB * 3 * NCHUNK, TPB>>>();
    finalize_kernel<<<NB, TPB>>>(out);
}

// round 6
// speedup vs baseline: 2.6344x; 1.7077x over previous
#include <cuda_runtime.h>

#define NPIX 22500
#define NB 32
#define NCHUNK 3
#define CHUNK 7500   // 22500 / 3
#define TPB 256
#define HB 64
#define LOB (-3.0f)
#define STEP (6.0f / 63.0f)
#define INV_SIG2 2500.0f   // 1 / 0.02^2
#define STRIDE 72          // SMEM row stride (floats): 72%32==8 -> conflict-free frags

// Scratch (no allocations allowed): prep data + per-chunk partial histograms
__device__ float g_prep[3 * NB * NPIX];                    // d01, d02, Iy planes
__device__ float g_part[NB * 3 * NCHUNK * HB * HB];        // one 64x64 partial per CTA

__device__ __forceinline__ float kq(float d) {
    // inverse-quadratic soft-bin kernel: 1 / (1 + d^2 / sigma^2)
    float q = fmaf(d * d, INV_SIG2, 1.0f);
    float r;
    asm("rcp.approx.f32 %0, %1;" : "=f"(r) : "f"(q));
    return r;
}

__device__ __forceinline__ unsigned tf32_of(float f) {
    unsigned r;
    asm("cvt.rna.tf32.f32 %0, %1;" : "=r"(r) : "f"(f));
    return r;
}

// ---------------------------------------------------------------------------
// Kernel 1: per-pixel prep — clip, logs, intensity
// ---------------------------------------------------------------------------
__global__ void __launch_bounds__(TPB) prep_kernel(const float* __restrict__ x) {
    int idx = blockIdx.x * blockDim.x + threadIdx.x;
    if (idx >= NB * NPIX) return;
    int b = idx / NPIX;
    int p = idx - b * NPIX;
    const float* xb = x + (size_t)b * 3 * NPIX;
    float r  = fminf(fmaxf(xb[p],            0.0f), 1.0f);
    float g  = fminf(fmaxf(xb[NPIX + p],     0.0f), 1.0f);
    float bl = fminf(fmaxf(xb[2 * NPIX + p], 0.0f), 1.0f);
    float iy = sqrtf(fmaf(r, r, fmaf(g, g, fmaf(bl, bl, 1e-6f))));
    float l0 = logf(r  + 1e-6f);
    float l1 = logf(g  + 1e-6f);
    float l2 = logf(bl + 1e-6f);
    g_prep[idx]                 = l0 - l1;   // d01
    g_prep[NB * NPIX + idx]     = l0 - l2;   // d02
    g_prep[2 * NB * NPIX + idx] = iy;
}

// ---------------------------------------------------------------------------
// Kernel 2: main — per (b, c, chunk) CTA, 32-pixel tiles, tf32 mma.sync.
//   Gen: threads 0-127 build A rows (iy*Ku, tf32), 128-255 build B rows (Kv).
//   Consume: 8 warps; warp w owns output tile rows [16*(w>>1)..+15],
//   cols [(w&1)*32..+31] via 4x m16n8k8 tf32 MMAs per 8-pixel k-step.
// ---------------------------------------------------------------------------
__global__ void __launch_bounds__(TPB, 2) hist_kernel() {
    __shared__ unsigned sKu[32 * STRIDE];   // tf32 bits of iy*Ku
    __shared__ unsigned sKv[32 * STRIDE];   // tf32 bits of Kv

    int cta   = blockIdx.x;           // 0 .. 96*NCHUNK-1
    int chunk = cta % NCHUNK;
    int bc    = cta / NCHUNK;
    int b     = bc / 3;
    int c     = bc - b * 3;

    int t    = threadIdx.x;
    int lane = t & 31;
    int w    = t >> 5;                // warp 0..7
    int gid  = lane >> 2;             // groupID 0..7
    int tig  = lane & 3;              // threadID_in_group 0..3
    int mg   = w >> 1;                // 0..3 -> output rows mg*16..
    int nb   = (w & 1) * 32;          // output col base 0 / 32

    // gen-phase mapping: warps 0-3 -> Ku (A), warps 4-7 -> Kv (B)
    bool isKu = (t < 128);
    int  gpix = (t & 127) >> 2;       // 0..31
    int  bin0 = (t & 3) * 16;         // 0,16,32,48

    float acc[4][4];                  // [n8-tile][c0..c3]
    #pragma unroll
    for (int i = 0; i < 4; ++i)
        #pragma unroll
        for (int j = 0; j < 4; ++j) acc[i][j] = 0.0f;

    const float* pd01 = g_prep + (size_t)b * NPIX;
    const float* pd02 = pd01 + (size_t)NB * NPIX;
    const float* piy  = pd01 + (size_t)2 * NB * NPIX;
    int p0 = chunk * CHUNK;

    const int NTILES = (CHUNK + 31) / 32;   // 235 (last tile partial)
    for (int tile = 0; tile < NTILES; ++tile) {
        // ---- generate tf32 Ku/Kv tables for 32 pixels ----
        int p = p0 + tile * 32 + gpix;
        float d01 = 0.0f, d02 = 0.0f, iy = 0.0f;
        if (p < p0 + CHUNK) {
            d01 = pd01[p];
            d02 = pd02[p];
            iy  = piy[p];    // OOB pixels: iy=0 -> A row 0 -> no contribution
        }
        float U, V;
        if (c == 0)      { U =  d01; V =  d02; }
        else if (c == 1) { U = -d01; V =  d02 - d01; }
        else             { U = -d02; V =  d01 - d02; }

        if (isKu) {
            float dBase = U - (LOB + (float)bin0 * STEP);
            #pragma unroll
            for (int q = 0; q < 4; ++q) {
                uint4 o;
                o.x = tf32_of(kq(dBase - (float)(4 * q + 0) * STEP) * iy);
                o.y = tf32_of(kq(dBase - (float)(4 * q + 1) * STEP) * iy);
                o.z = tf32_of(kq(dBase - (float)(4 * q + 2) * STEP) * iy);
                o.w = tf32_of(kq(dBase - (float)(4 * q + 3) * STEP) * iy);
                *reinterpret_cast<uint4*>(&sKu[gpix * STRIDE + bin0 + 4 * q]) = o;
            }
        } else {
            float dBase = V - (LOB + (float)bin0 * STEP);
            #pragma unroll
            for (int q = 0; q < 4; ++q) {
                uint4 o;
                o.x = tf32_of(kq(dBase - (float)(4 * q + 0) * STEP));
                o.y = tf32_of(kq(dBase - (float)(4 * q + 1) * STEP));
                o.z = tf32_of(kq(dBase - (float)(4 * q + 2) * STEP));
                o.w = tf32_of(kq(dBase - (float)(4 * q + 3) * STEP));
                *reinterpret_cast<uint4*>(&sKv[gpix * STRIDE + bin0 + 4 * q]) = o;
            }
        }
        __syncthreads();

        // ---- consume: 4 k-steps of 8 pixels, 4 n8-tiles per warp ----
        #pragma unroll
        for (int kb = 0; kb < 4; ++kb) {
            const unsigned* ru = &sKu[(kb * 8 + tig) * STRIDE];
            const unsigned* rv = &sKv[(kb * 8 + tig) * STRIDE];
            unsigned a0 = ru[mg * 16 + gid];                    // (u=mg16+gid, k=tig)
            unsigned a1 = ru[mg * 16 + gid + 8];                // (u+8,        k=tig)
            unsigned a2 = ru[4 * STRIDE + mg * 16 + gid];       // (u,          k=tig+4)
            unsigned a3 = ru[4 * STRIDE + mg * 16 + gid + 8];   // (u+8,        k=tig+4)
            #pragma unroll
            for (int tl = 0; tl < 4; ++tl) {
                unsigned b0 = rv[nb + tl * 8 + gid];                // (k=tig,   v=nb+tl8+gid)
                unsigned b1 = rv[4 * STRIDE + nb + tl * 8 + gid];   // (k=tig+4, v)
                asm("mma.sync.aligned.m16n8k8.row.col.f32.tf32.tf32.f32 "
                    "{%0,%1,%2,%3}, {%4,%5,%6,%7}, {%8,%9}, {%0,%1,%2,%3};"
                    : "+f"(acc[tl][0]), "+f"(acc[tl][1]),
                      "+f"(acc[tl][2]), "+f"(acc[tl][3])
                    : "r"(a0), "r"(a1), "r"(a2), "r"(a3), "r"(b0), "r"(b1));
            }
        }
        __syncthreads();
    }

    // write this CTA's 64x64 partial (deterministic, no atomics)
    float* base = g_part + (size_t)cta * (HB * HB);
    int row0 = mg * 16 + gid;
    #pragma unroll
    for (int tl = 0; tl < 4; ++tl) {
        int col = nb + tl * 8 + 2 * tig;
        float2 lo; lo.x = acc[tl][0]; lo.y = acc[tl][1];
        float2 hi; hi.x = acc[tl][2]; hi.y = acc[tl][3];
        *reinterpret_cast<float2*>(base + row0 * HB + col)       = lo;
        *reinterpret_cast<float2*>(base + (row0 + 8) * HB + col) = hi;
    }
}

// ---------------------------------------------------------------------------
// Kernel 3: reduce NCHUNK partials per (b,c), per-batch normalize, write out
// ---------------------------------------------------------------------------
#define NPART NCHUNK
__global__ void __launch_bounds__(TPB) finalize_kernel(float* __restrict__ out) {
    int b = blockIdx.x;
    int t = threadIdx.x;
    float vals[48];
    float local = 0.0f;
    #pragma unroll
    for (int j = 0; j < 48; ++j) {
        int vi = t + TPB * j;            // 0 .. 12287 = c*4096 + u*64 + v
        int c  = vi >> 12;
        int uv = vi & 4095;
        const float* part = g_part + (size_t)(b * 3 + c) * NPART * 4096 + uv;
        float s = 0.0f;
        #pragma unroll
        for (int k = 0; k < NPART; ++k) s += part[k * 4096];
        vals[j] = s;
        local  += s;
    }
    __shared__ float red[TPB];
    red[t] = local;
    __syncthreads();
    #pragma unroll
    for (int s = TPB / 2; s > 0; s >>= 1) {
        if (t < s) red[t] += red[t + s];
        __syncthreads();
    }
    float inv = 1.0f / (red[0] + 1e-6f);
    #pragma unroll
    for (int j = 0; j < 48; ++j) {
        out[(size_t)b * 12288 + t + TPB * j] = vals[j] * inv;
    }
}

// ---------------------------------------------------------------------------
extern "C" void kernel_launch(void* const* d_in, const int* in_sizes, int n_in,
                              void* d_out, int out_size) {
    const float* x = (const float*)d_in[0];
    float* out = (float*)d_out;
    prep_kernel<<<(NB * NPIX + TPB - 1) / TPB, TPB>>>(x);
    hist_kernel<<<NB * 3 * NCHUNK, TPB>>>();
    finalize_kernel<<<NB, TPB>>>(out);
}

// round 7
// speedup vs baseline: 2.6897x; 1.0210x over previous
#include <cuda_runtime.h>

#define NPIX 22500
#define NB 32
#define NCHUNK 3
#define CHUNK 7500   // 22500 / 3
#define TPB 256
#define HB 64
#define LOB (-3.0f)
#define STEP (6.0f / 63.0f)
#define INV_SIG2 2500.0f   // 1 / 0.02^2
#define STRIDE 72          // SMEM row stride (floats): 72%32==8 -> conflict-free frags

// Scratch (no allocations allowed): prep data + per-chunk partial histograms
__device__ float g_prep[3 * NB * NPIX];                    // d01, d02, Iy planes
__device__ float g_part[NB * 3 * NCHUNK * HB * HB];        // one 64x64 partial per CTA

__device__ __forceinline__ float kq(float d) {
    // inverse-quadratic soft-bin kernel: 1 / (1 + d^2 / sigma^2)
    float q = fmaf(d * d, INV_SIG2, 1.0f);
    float r;
    asm("rcp.approx.f32 %0, %1;" : "=f"(r) : "f"(q));
    return r;
}

__device__ __forceinline__ unsigned tf32_of(float f) {
    unsigned r;
    asm("cvt.rna.tf32.f32 %0, %1;" : "=r"(r) : "f"(f));
    return r;
}

// ---------------------------------------------------------------------------
// Kernel 1: per-pixel prep — clip, logs, intensity
// ---------------------------------------------------------------------------
__global__ void __launch_bounds__(TPB) prep_kernel(const float* __restrict__ x) {
    int idx = blockIdx.x * blockDim.x + threadIdx.x;
    if (idx >= NB * NPIX) return;
    int b = idx / NPIX;
    int p = idx - b * NPIX;
    const float* xb = x + (size_t)b * 3 * NPIX;
    float r  = fminf(fmaxf(xb[p],            0.0f), 1.0f);
    float g  = fminf(fmaxf(xb[NPIX + p],     0.0f), 1.0f);
    float bl = fminf(fmaxf(xb[2 * NPIX + p], 0.0f), 1.0f);
    float iy = sqrtf(fmaf(r, r, fmaf(g, g, fmaf(bl, bl, 1e-6f))));
    float l0 = logf(r  + 1e-6f);
    float l1 = logf(g  + 1e-6f);
    float l2 = logf(bl + 1e-6f);
    g_prep[idx]                 = l0 - l1;   // d01
    g_prep[NB * NPIX + idx]     = l0 - l2;   // d02
    g_prep[2 * NB * NPIX + idx] = iy;
}

// ---------------------------------------------------------------------------
// Kernel 2: main — per (b, c, chunk) CTA, 32-pixel tiles, tf32 mma.sync,
//   DOUBLE-BUFFERED: gen of tile t+1 interleaves with consume of tile t,
//   one __syncthreads per tile. MUFU gen work overlaps tensor/LDS work.
// ---------------------------------------------------------------------------
__device__ __forceinline__ void gen_tile(
    unsigned* __restrict__ bKu, unsigned* __restrict__ bKv,
    const float* __restrict__ pd01, const float* __restrict__ pd02,
    const float* __restrict__ piy,
    int p0, int tile, int c, bool isKu, int gpix, int bin0)
{
    int p = p0 + tile * 32 + gpix;
    float d01 = 0.0f, d02 = 0.0f, iy = 0.0f;
    if (p < p0 + CHUNK) {
        d01 = pd01[p];
        d02 = pd02[p];
        iy  = piy[p];    // OOB pixels: iy=0 -> A row 0 -> no contribution
    }
    float U, V;
    if (c == 0)      { U =  d01; V =  d02; }
    else if (c == 1) { U = -d01; V =  d02 - d01; }
    else             { U = -d02; V =  d01 - d02; }

    if (isKu) {
        float dBase = U - (LOB + (float)bin0 * STEP);
        #pragma unroll
        for (int q = 0; q < 4; ++q) {
            uint4 o;
            o.x = tf32_of(kq(dBase - (float)(4 * q + 0) * STEP) * iy);
            o.y = tf32_of(kq(dBase - (float)(4 * q + 1) * STEP) * iy);
            o.z = tf32_of(kq(dBase - (float)(4 * q + 2) * STEP) * iy);
            o.w = tf32_of(kq(dBase - (float)(4 * q + 3) * STEP) * iy);
            *reinterpret_cast<uint4*>(&bKu[gpix * STRIDE + bin0 + 4 * q]) = o;
        }
    } else {
        float dBase = V - (LOB + (float)bin0 * STEP);
        #pragma unroll
        for (int q = 0; q < 4; ++q) {
            uint4 o;
            o.x = tf32_of(kq(dBase - (float)(4 * q + 0) * STEP));
            o.y = tf32_of(kq(dBase - (float)(4 * q + 1) * STEP));
            o.z = tf32_of(kq(dBase - (float)(4 * q + 2) * STEP));
            o.w = tf32_of(kq(dBase - (float)(4 * q + 3) * STEP));
            *reinterpret_cast<uint4*>(&bKv[gpix * STRIDE + bin0 + 4 * q]) = o;
        }
    }
}

__device__ __forceinline__ void consume_tile(
    const unsigned* __restrict__ bKu, const unsigned* __restrict__ bKv,
    float acc[4][4], int mg, int nb, int gid, int tig)
{
    #pragma unroll
    for (int kb = 0; kb < 4; ++kb) {
        const unsigned* ru = &bKu[(kb * 8 + tig) * STRIDE];
        const unsigned* rv = &bKv[(kb * 8 + tig) * STRIDE];
        unsigned a0 = ru[mg * 16 + gid];                    // (u=mg16+gid, k=tig)
        unsigned a1 = ru[mg * 16 + gid + 8];                // (u+8,        k=tig)
        unsigned a2 = ru[4 * STRIDE + mg * 16 + gid];       // (u,          k=tig+4)
        unsigned a3 = ru[4 * STRIDE + mg * 16 + gid + 8];   // (u+8,        k=tig+4)
        #pragma unroll
        for (int tl = 0; tl < 4; ++tl) {
            unsigned b0 = rv[nb + tl * 8 + gid];                // (k=tig,   v)
            unsigned b1 = rv[4 * STRIDE + nb + tl * 8 + gid];   // (k=tig+4, v)
            asm("mma.sync.aligned.m16n8k8.row.col.f32.tf32.tf32.f32 "
                "{%0,%1,%2,%3}, {%4,%5,%6,%7}, {%8,%9}, {%0,%1,%2,%3};"
                : "+f"(acc[tl][0]), "+f"(acc[tl][1]),
                  "+f"(acc[tl][2]), "+f"(acc[tl][3])
                : "r"(a0), "r"(a1), "r"(a2), "r"(a3), "r"(b0), "r"(b1));
        }
    }
}

__global__ void __launch_bounds__(TPB, 2) hist_kernel() {
    __shared__ unsigned sKu[2][32 * STRIDE];   // tf32 bits of iy*Ku (ping-pong)
    __shared__ unsigned sKv[2][32 * STRIDE];   // tf32 bits of Kv    (ping-pong)

    int cta   = blockIdx.x;           // 0 .. 96*NCHUNK-1
    int chunk = cta % NCHUNK;
    int bc    = cta / NCHUNK;
    int b     = bc / 3;
    int c     = bc - b * 3;

    int t    = threadIdx.x;
    int lane = t & 31;
    int w    = t >> 5;                // warp 0..7
    int gid  = lane >> 2;             // groupID 0..7
    int tig  = lane & 3;              // threadID_in_group 0..3
    int mg   = w >> 1;                // 0..3 -> output rows mg*16..
    int nb   = (w & 1) * 32;          // output col base 0 / 32

    // gen-phase mapping: warps 0-3 -> Ku (A), warps 4-7 -> Kv (B)
    bool isKu = (t < 128);
    int  gpix = (t & 127) >> 2;       // 0..31
    int  bin0 = (t & 3) * 16;         // 0,16,32,48

    float acc[4][4];                  // [n8-tile][c0..c3]
    #pragma unroll
    for (int i = 0; i < 4; ++i)
        #pragma unroll
        for (int j = 0; j < 4; ++j) acc[i][j] = 0.0f;

    const float* pd01 = g_prep + (size_t)b * NPIX;
    const float* pd02 = pd01 + (size_t)NB * NPIX;
    const float* piy  = pd01 + (size_t)2 * NB * NPIX;
    int p0 = chunk * CHUNK;

    const int NTILES = (CHUNK + 31) / 32;   // 235 (last tile partial)

    // prologue: fill buffer 0
    gen_tile(sKu[0], sKv[0], pd01, pd02, piy, p0, 0, c, isKu, gpix, bin0);
    __syncthreads();

    for (int tile = 0; tile < NTILES; ++tile) {
        int cur = tile & 1;
        int nxt = cur ^ 1;
        if (tile + 1 < NTILES)
            gen_tile(sKu[nxt], sKv[nxt], pd01, pd02, piy,
                     p0, tile + 1, c, isKu, gpix, bin0);
        consume_tile(sKu[cur], sKv[cur], acc, mg, nb, gid, tig);
        __syncthreads();
    }

    // write this CTA's 64x64 partial (deterministic, no atomics)
    float* base = g_part + (size_t)cta * (HB * HB);
    int row0 = mg * 16 + gid;
    #pragma unroll
    for (int tl = 0; tl < 4; ++tl) {
        int col = nb + tl * 8 + 2 * tig;
        float2 lo; lo.x = acc[tl][0]; lo.y = acc[tl][1];
        float2 hi; hi.x = acc[tl][2]; hi.y = acc[tl][3];
        *reinterpret_cast<float2*>(base + row0 * HB + col)       = lo;
        *reinterpret_cast<float2*>(base + (row0 + 8) * HB + col) = hi;
    }
}

// ---------------------------------------------------------------------------
// Kernel 3: reduce NCHUNK partials per (b,c), per-batch normalize, write out
// ---------------------------------------------------------------------------
#define NPART NCHUNK
__global__ void __launch_bounds__(TPB) finalize_kernel(float* __restrict__ out) {
    int b = blockIdx.x;
    int t = threadIdx.x;
    float vals[48];
    float local = 0.0f;
    #pragma unroll
    for (int j = 0; j < 48; ++j) {
        int vi = t + TPB * j;            // 0 .. 12287 = c*4096 + u*64 + v
        int c  = vi >> 12;
        int uv = vi & 4095;
        const float* part = g_part + (size_t)(b * 3 + c) * NPART * 4096 + uv;
        float s = 0.0f;
        #pragma unroll
        for (int k = 0; k < NPART; ++k) s += part[k * 4096];
        vals[j] = s;
        local  += s;
    }
    __shared__ float red[TPB];
    red[t] = local;
    __syncthreads();
    #pragma unroll
    for (int s = TPB / 2; s > 0; s >>= 1) {
        if (t < s) red[t] += red[t + s];
        __syncthreads();
    }
    float inv = 1.0f / (red[0] + 1e-6f);
    #pragma unroll
    for (int j = 0; j < 48; ++j) {
        out[(size_t)b * 12288 + t + TPB * j] = vals[j] * inv;
    }
}

// ---------------------------------------------------------------------------
extern "C" void kernel_launch(void* const* d_in, const int* in_sizes, int n_in,
                              void* d_out, int out_size) {
    const float* x = (const float*)d_in[0];
    float* out = (float*)d_out;
    prep_kernel<<<(NB * NPIX + TPB - 1) / TPB, TPB>>>(x);
    hist_kernel<<<NB * 3 * NCHUNK, TPB>>>();
    finalize_kernel<<<NB, TPB>>>(out);
}

// round 9
// speedup vs baseline: 4.8080x; 1.7875x over previous
#include <cuda_runtime.h>

#define NPIX 22500
#define NB 32
#define NCHUNK 9
#define CHUNK 2500   // 22500 / 9
#define TPB 256
#define HB 64
#define LOB (-3.0f)
#define STEP (6.0f / 63.0f)
#define INV_SIG2 2500.0f   // 1 / 0.02^2
#define STRIDE 72          // fp16x2-words per table row: 72%32==8 -> conflict-free
#define TABW (16 * STRIDE) // words per table (16 pixel-pairs)

// Scratch (no allocations allowed)
__device__ float g_prep[3 * NB * NPIX];                    // d01, d02, Iy planes
__device__ float g_part[NB * 3 * NCHUNK * HB * HB];        // 64x64 partial per (b,c,chunk)

__device__ __forceinline__ float kq(float d) {
    float q = fmaf(d * d, INV_SIG2, 1.0f);
    float r;
    asm("rcp.approx.f32 %0, %1;" : "=f"(r) : "f"(q));
    return r;
}

// pack {lo=f0, hi=f1} as fp16x2
__device__ __forceinline__ unsigned pack_h2(float f0, float f1) {
    unsigned r;
    asm("cvt.rn.f16x2.f32 %0, %1, %2;" : "=r"(r) : "f"(f1), "f"(f0));
    return r;
}

// ---------------------------------------------------------------------------
// Kernel 1: per-pixel prep — clip, logs, intensity
// ---------------------------------------------------------------------------
__global__ void __launch_bounds__(TPB) prep_kernel(const float* __restrict__ x) {
    int idx = blockIdx.x * blockDim.x + threadIdx.x;
    if (idx >= NB * NPIX) return;
    int b = idx / NPIX;
    int p = idx - b * NPIX;
    const float* xb = x + (size_t)b * 3 * NPIX;
    float r  = fminf(fmaxf(xb[p],            0.0f), 1.0f);
    float g  = fminf(fmaxf(xb[NPIX + p],     0.0f), 1.0f);
    float bl = fminf(fmaxf(xb[2 * NPIX + p], 0.0f), 1.0f);
    float iy = sqrtf(fmaf(r, r, fmaf(g, g, fmaf(bl, bl, 1e-6f))));
    float l0 = logf(r  + 1e-6f);
    float l1 = logf(g  + 1e-6f);
    float l2 = logf(bl + 1e-6f);
    g_prep[idx]                 = l0 - l1;   // d01
    g_prep[NB * NPIX + idx]     = l0 - l2;   // d02
    g_prep[2 * NB * NPIX + idx] = iy;
}

// ---------------------------------------------------------------------------
// Kernel 2: main — per (b, chunk) CTA, ALL 3 channels, fp16 m16n8k16 MMA.
//   Tables per 32-px tile (fp16x2, 2 adjacent pixels packed per word):
//     T0 = iy*K(d01)   [A c0; mirrored A c1]
//     T1 = K(d02)      [B c0; mirrored A c2]
//     T2 = K(d12)      [B c1]
//     T3 = iy*K(d12)   [mirrored B c2]
//   Mirrors use bin index 63-x (kq even + symmetric bins). Double-buffered.
// ---------------------------------------------------------------------------
__device__ __forceinline__ void gen_tile(
    unsigned* __restrict__ buf,
    const float* __restrict__ pd01, const float* __restrict__ pd02,
    const float* __restrict__ piy,
    int p0, int tile, int job, int pair, int slot)
{
    int px0 = p0 + tile * 32 + 2 * pair;
    int px1 = px0 + 1;
    int pe  = p0 + CHUNK;
    float a01 = 0.f, a02 = 0.f, aiy = 0.f;
    float b01 = 0.f, b02 = 0.f, biy = 0.f;
    if (px0 < pe) { a01 = pd01[px0]; a02 = pd02[px0]; aiy = piy[px0]; }
    if (px1 < pe) { b01 = pd01[px1]; b02 = pd02[px1]; biy = piy[px1]; }

    float v0, v1, s0, s1;
    if (job == 0)      { v0 = a01;       v1 = b01;       s0 = aiy; s1 = biy; }
    else if (job == 1) { v0 = a02;       v1 = b02;       s0 = 1.f; s1 = 1.f; }
    else if (job == 2) { v0 = a02 - a01; v1 = b02 - b01; s0 = 1.f; s1 = 1.f; }
    else               { v0 = a02 - a01; v1 = b02 - b01; s0 = aiy; s1 = biy; }

    int bin0 = slot * 16;
    float dB0 = v0 - (LOB + (float)bin0 * STEP);
    float dB1 = v1 - (LOB + (float)bin0 * STEP);
    unsigned h[16];
    #pragma unroll
    for (int i = 0; i < 16; ++i) {
        float k0 = kq(dB0 - (float)i * STEP) * s0;
        float k1 = kq(dB1 - (float)i * STEP) * s1;
        h[i] = pack_h2(k0, k1);
    }
    unsigned* dst = buf + job * TABW + pair * STRIDE + bin0;
    #pragma unroll
    for (int q = 0; q < 4; ++q)
        *reinterpret_cast<uint4*>(dst + 4 * q) =
            make_uint4(h[4*q], h[4*q+1], h[4*q+2], h[4*q+3]);
}

#define HMMA_F16(ACC, A0, A1, A2, A3, B0, B1)                                \
    asm("mma.sync.aligned.m16n8k16.row.col.f32.f16.f16.f32 "                 \
        "{%0,%1,%2,%3}, {%4,%5,%6,%7}, {%8,%9}, {%0,%1,%2,%3};"              \
        : "+f"((ACC)[0]), "+f"((ACC)[1]), "+f"((ACC)[2]), "+f"((ACC)[3])     \
        : "r"(A0), "r"(A1), "r"(A2), "r"(A3), "r"(B0), "r"(B1))

__device__ __forceinline__ void consume_tile(
    const unsigned* __restrict__ buf,
    float acc[3][4][4], int mg, int nb, int gid, int tig)
{
    const unsigned* T0 = buf;
    const unsigned* T1 = buf + TABW;
    const unsigned* T2 = buf + 2 * TABW;
    const unsigned* T3 = buf + 3 * TABW;
    int ub = mg * 16 + gid;       // u-bin (direct)
    int um = 63 - ub;             // u-bin (mirrored); um-8 pairs with ub+8
    #pragma unroll
    for (int kb = 0; kb < 2; ++kb) {
        int r0 = (8 * kb + tig) * STRIDE;
        int r1 = r0 + 4 * STRIDE;
        // c0: A = T0 direct
        unsigned c0a0 = T0[r0 + ub], c0a1 = T0[r0 + ub + 8];
        unsigned c0a2 = T0[r1 + ub], c0a3 = T0[r1 + ub + 8];
        // c1: A = T0 mirrored
        unsigned c1a0 = T0[r0 + um], c1a1 = T0[r0 + um - 8];
        unsigned c1a2 = T0[r1 + um], c1a3 = T0[r1 + um - 8];
        // c2: A = T1 mirrored
        unsigned c2a0 = T1[r0 + um], c2a1 = T1[r0 + um - 8];
        unsigned c2a2 = T1[r1 + um], c2a3 = T1[r1 + um - 8];
        #pragma unroll
        for (int tl = 0; tl < 4; ++tl) {
            int vb = nb + tl * 8 + gid;
            int vm = 63 - vb;
            unsigned b0, b1;
            b0 = T1[r0 + vb]; b1 = T1[r1 + vb];              // c0: B = K02
            HMMA_F16(acc[0][tl], c0a0, c0a1, c0a2, c0a3, b0, b1);
            b0 = T2[r0 + vb]; b1 = T2[r1 + vb];              // c1: B = K12
            HMMA_F16(acc[1][tl], c1a0, c1a1, c1a2, c1a3, b0, b1);
            b0 = T3[r0 + vm]; b1 = T3[r1 + vm];              // c2: B = mirror(iyK12)
            HMMA_F16(acc[2][tl], c2a0, c2a1, c2a2, c2a3, b0, b1);
        }
    }
}

__global__ void __launch_bounds__(TPB, 2) hist_kernel() {
    __shared__ unsigned sTab[2][4 * TABW];   // 2 x 18 KB ping-pong

    int cta   = blockIdx.x;           // 0 .. NB*NCHUNK-1
    int chunk = cta % NCHUNK;
    int b     = cta / NCHUNK;

    int t    = threadIdx.x;
    int lane = t & 31;
    int w    = t >> 5;                // warp 0..7
    int gid  = lane >> 2;             // groupID 0..7
    int tig  = lane & 3;              // threadID_in_group 0..3
    int mg   = w >> 1;                // output rows mg*16..
    int nb   = (w & 1) * 32;          // output col base 0 / 32

    // gen mapping: job per warp-pair, 4 threads per (job, pixel-pair) row
    int job  = t >> 6;                // 0..3 (warp-uniform)
    int rem  = t & 63;
    int pair = rem >> 2;              // 0..15
    int slot = rem & 3;               // 16-bin range

    float acc[3][4][4];
    #pragma unroll
    for (int c = 0; c < 3; ++c)
        #pragma unroll
        for (int i = 0; i < 4; ++i)
            #pragma unroll
            for (int j = 0; j < 4; ++j) acc[c][i][j] = 0.0f;

    const float* pd01 = g_prep + (size_t)b * NPIX;
    const float* pd02 = pd01 + (size_t)NB * NPIX;
    const float* piy  = pd01 + (size_t)2 * NB * NPIX;
    int p0 = chunk * CHUNK;

    const int NTILES = (CHUNK + 31) / 32;   // 79 (last tile has 4 px)

    gen_tile(sTab[0], pd01, pd02, piy, p0, 0, job, pair, slot);
    __syncthreads();

    for (int tile = 0; tile < NTILES; ++tile) {
        int cur = tile & 1;
        int nxt = cur ^ 1;
        if (tile + 1 < NTILES)
            gen_tile(sTab[nxt], pd01, pd02, piy, p0, tile + 1, job, pair, slot);
        consume_tile(sTab[cur], acc, mg, nb, gid, tig);
        __syncthreads();
    }

    // write 3 partials (deterministic, no atomics)
    int row0 = mg * 16 + gid;
    #pragma unroll
    for (int c = 0; c < 3; ++c) {
        float* base = g_part + ((size_t)(b * 3 + c) * NCHUNK + chunk) * (HB * HB);
        #pragma unroll
        for (int tl = 0; tl < 4; ++tl) {
            int col = nb + tl * 8 + 2 * tig;
            float2 lo; lo.x = acc[c][tl][0]; lo.y = acc[c][tl][1];
            float2 hi; hi.x = acc[c][tl][2]; hi.y = acc[c][tl][3];
            *reinterpret_cast<float2*>(base + row0 * HB + col)       = lo;
            *reinterpret_cast<float2*>(base + (row0 + 8) * HB + col) = hi;
        }
    }
}

// ---------------------------------------------------------------------------
// Kernel 3: reduce NCHUNK partials per (b,c), per-batch normalize, write out
// ---------------------------------------------------------------------------
__global__ void __launch_bounds__(TPB) finalize_kernel(float* __restrict__ out) {
    int b = blockIdx.x;
    int t = threadIdx.x;
    float vals[48];
    float local = 0.0f;
    #pragma unroll
    for (int j = 0; j < 48; ++j) {
        int vi = t + TPB * j;            // 0 .. 12287 = c*4096 + u*64 + v
        int c  = vi >> 12;
        int uv = vi & 4095;
        const float* part = g_part + (size_t)(b * 3 + c) * NCHUNK * 4096 + uv;
        float s = 0.0f;
        #pragma unroll
        for (int k = 0; k < NCHUNK; ++k) s += part[k * 4096];
        vals[j] = s;
        local  += s;
    }
    __shared__ float red[TPB];
    red[t] = local;
    __syncthreads();
    #pragma unroll
    for (int s = TPB / 2; s > 0; s >>= 1) {
        if (t < s) red[t] += red[t + s];
        __syncthreads();
    }
    float inv = 1.0f / (red[0] + 1e-6f);
    #pragma unroll
    for (int j = 0; j < 48; ++j) {
        out[(size_t)b * 12288 + t + TPB * j] = vals[j] * inv;
    }
}

// ---------------------------------------------------------------------------
extern "C" void kernel_launch(void* const* d_in, const int* in_sizes, int n_in,
                              void* d_out, int out_size) {
    const float* x = (const float*)d_in[0];
    float* out = (float*)d_out;
    prep_kernel<<<(NB * NPIX + TPB - 1) / TPB, TPB>>>(x);
    hist_kernel<<<NB * NCHUNK, TPB>>>();
    finalize_kernel<<<NB, TPB>>>(out);
}